// round 3
// baseline (speedup 1.0000x reference)
#include <cuda_runtime.h>
#include <cuda_bf16.h>
#include <cstdint>

#define DEV_INLINE __device__ __forceinline__

// ---------------- problem dims (fixed by reference) ----------------
constexpr int M_TOK = 8 * 2048;   // 16384 tokens
constexpr int NE    = 1024;       // n_embd
constexpr int DFF   = 4096;       // 4*n_embd
constexpr int RANK  = 4;
constexpr float LORA_SCALE = 0.25f;

// ---------------- device scratch (allocation-free rule: __device__ globals) ----------------
__device__ __nv_bfloat16 g_xh[(size_t)M_TOK * NE];
__device__ __nv_bfloat16 g_xl[(size_t)M_TOK * NE];
__device__ __nv_bfloat16 g_w1h[(size_t)DFF * NE];
__device__ __nv_bfloat16 g_w1l[(size_t)DFF * NE];
__device__ __nv_bfloat16 g_w2h[(size_t)NE * DFF];
__device__ __nv_bfloat16 g_w2l[(size_t)NE * DFF];
__device__ __nv_bfloat16 g_hh[(size_t)M_TOK * DFF];
__device__ __nv_bfloat16 g_hl[(size_t)M_TOK * DFF];
__device__ __align__(16) float g_t1[(size_t)M_TOK * RANK];
__device__ __align__(16) float g_t2[(size_t)M_TOK * RANK];

// ---------------- PTX helpers (family-portable only: cp.async, ldmatrix, mma.sync) ----------------
DEV_INLINE uint32_t smem_u32(const void* p) {
    uint32_t a;
    asm("{ .reg .u64 t; cvta.to.shared.u64 t, %1; cvt.u32.u64 %0, t; }" : "=r"(a) : "l"(p));
    return a;
}

#define CP_ASYNC16(dst, src) \
    asm volatile("cp.async.cg.shared.global [%0], [%1], 16;" :: "r"(dst), "l"(src))
#define CP_COMMIT() asm volatile("cp.async.commit_group;" ::: "memory")

template <int N>
DEV_INLINE void cp_wait() { asm volatile("cp.async.wait_group %0;" :: "n"(N) : "memory"); }

DEV_INLINE void ldsm_x4(uint32_t r[4], uint32_t addr) {
    asm volatile("ldmatrix.sync.aligned.m8n8.x4.shared.b16 {%0,%1,%2,%3}, [%4];"
                 : "=r"(r[0]), "=r"(r[1]), "=r"(r[2]), "=r"(r[3]) : "r"(addr));
}

DEV_INLINE void mma_bf16(float c[4], const uint32_t a[4], const uint32_t* b) {
    asm volatile(
        "mma.sync.aligned.m16n8k16.row.col.f32.bf16.bf16.f32 "
        "{%0,%1,%2,%3}, {%4,%5,%6,%7}, {%8,%9}, {%0,%1,%2,%3};"
        : "+f"(c[0]), "+f"(c[1]), "+f"(c[2]), "+f"(c[3])
        : "r"(a[0]), "r"(a[1]), "r"(a[2]), "r"(a[3]), "r"(b[0]), "r"(b[1]));
}

// ---------------- GEMM config ----------------
constexpr int BM = 128, BN = 128, BK = 64, STAGES = 3;
constexpr int ROWB    = BK * 2;                // 128 bytes per swizzled row
constexpr int TILE_B  = BM * ROWB;             // 16 KB
constexpr int STAGE_B = 4 * TILE_B;            // Ah, Al, Bh, Bl = 64 KB
constexpr int SMEM_GEMM = STAGES * STAGE_B;    // 192 KB

// Load one 128x64 bf16 tile into XOR-crosswise swizzled SMEM (16B granule c16 at
// column c16 ^ (row & 7)). Conflict-free for both these stores and ldmatrix.
DEV_INLINE void load_tile(uint32_t sdst, const __nv_bfloat16* g, int r0, int kc,
                          int ldK, int tid) {
    const char* gb = reinterpret_cast<const char*>(g);
#pragma unroll
    for (int i = 0; i < 4; ++i) {
        int gidx = tid + i * 256;
        int row = gidx >> 3;
        int c16 = gidx & 7;
        uint32_t dst = sdst + row * ROWB + ((c16 ^ (row & 7)) << 4);
        const char* src = gb + ((size_t)(r0 + row) * ldK + kc + c16 * 8) * 2;
        CP_ASYNC16(dst, src);
    }
}

DEV_INLINE void load_stage(uint32_t s_stage,
                           const __nv_bfloat16* Ah, const __nv_bfloat16* Al,
                           const __nv_bfloat16* Bh, const __nv_bfloat16* Bl,
                           int m0, int n0, int kc, int K, int tid) {
    load_tile(s_stage + 0 * TILE_B, Ah, m0, kc, K, tid);
    load_tile(s_stage + 1 * TILE_B, Al, m0, kc, K, tid);
    load_tile(s_stage + 2 * TILE_B, Bh, n0, kc, K, tid);
    load_tile(s_stage + 3 * TILE_B, Bl, n0, kc, K, tid);
}

// ---------------- fused GEMM: D = A*B^T (bf16x3 split) + LoRA ----------------
// SPLIT_RELU ? (relu + write bf16 hi/lo pair) : (write fp32)
template <bool SPLIT_RELU>
__global__ void __launch_bounds__(256, 1)
gemm_hmma_kernel(const __nv_bfloat16* __restrict__ Ah, const __nv_bfloat16* __restrict__ Al,
                 const __nv_bfloat16* __restrict__ Bh, const __nv_bfloat16* __restrict__ Bl,
                 int K, int Ntot,
                 const float* __restrict__ t_vec,       // [M_TOK, RANK]
                 const float* __restrict__ Blora_base,  // [NUM_LOOPS, Ntot, RANK]
                 const int* __restrict__ id_ptr,
                 __nv_bfloat16* __restrict__ Oh, __nv_bfloat16* __restrict__ Ol,
                 float* __restrict__ Of) {
    extern __shared__ char smem[];
    const uint32_t sbase = smem_u32(smem);
    const int tid  = threadIdx.x;
    const int lane = tid & 31;
    const int warp = tid >> 5;
    const int wm = warp >> 2;   // 0..1 : warp m-tile (64 rows)
    const int wn = warp & 3;    // 0..3 : warp n-tile (32 cols)

    const int m0 = blockIdx.y * BM;
    const int n0 = blockIdx.x * BN;
    const int NC = K / BK;

    float acc[4][4][4];
#pragma unroll
    for (int i = 0; i < 4; ++i)
#pragma unroll
        for (int j = 0; j < 4; ++j)
#pragma unroll
            for (int e = 0; e < 4; ++e) acc[i][j][e] = 0.0f;

    // prologue: fill STAGES-1 stages
#pragma unroll
    for (int s = 0; s < STAGES - 1; ++s) {
        load_stage(sbase + s * STAGE_B, Ah, Al, Bh, Bl, m0, n0, s * BK, K, tid);
        CP_COMMIT();
    }

    // per-thread fragment address components (XOR swizzle)
    const int arow = wm * 64 + (lane & 15);            // A: rows m, ldmatrix x4
    const int brow = wn * 32 + ((lane >> 4) << 3) + (lane & 7);  // B: two n8 tiles per x4
    const int sw   = lane & 7;                         // row & 7 for both (tiles are 8-aligned)

    for (int c = 0; c < NC; ++c) {
        const int pre = c + STAGES - 1;
        if (pre < NC) {
            load_stage(sbase + (pre % STAGES) * STAGE_B, Ah, Al, Bh, Bl,
                       m0, n0, pre * BK, K, tid);
            CP_COMMIT();
            cp_wait<STAGES - 1>();
        } else if (c == NC - 2) {
            cp_wait<1>();
        } else {
            cp_wait<0>();
        }
        __syncthreads();

        const uint32_t st  = sbase + (c % STAGES) * STAGE_B;
        const uint32_t stAh = st + 0 * TILE_B + arow * ROWB;
        const uint32_t stAl = st + 1 * TILE_B + arow * ROWB;
        const uint32_t stBh = st + 2 * TILE_B + brow * ROWB;
        const uint32_t stBl = st + 3 * TILE_B + brow * ROWB;

#pragma unroll
        for (int ks = 0; ks < 4; ++ks) {   // 4 x k16 per 64-K chunk
            const uint32_t axo = (uint32_t)(((ks * 2 + (lane >> 4)) ^ sw) << 4);
            const uint32_t bxo = (uint32_t)(((ks * 2 + ((lane >> 3) & 1)) ^ sw) << 4);

            uint32_t ah[4][4], al[4][4], bh[2][4], bl[2][4];
#pragma unroll
            for (int mt = 0; mt < 4; ++mt) {
                ldsm_x4(ah[mt], stAh + mt * 16 * ROWB + axo);
                ldsm_x4(al[mt], stAl + mt * 16 * ROWB + axo);
            }
#pragma unroll
            for (int np = 0; np < 2; ++np) {
                ldsm_x4(bh[np], stBh + np * 16 * ROWB + bxo);
                ldsm_x4(bl[np], stBl + np * 16 * ROWB + bxo);
            }
#pragma unroll
            for (int mt = 0; mt < 4; ++mt) {
#pragma unroll
                for (int nt = 0; nt < 4; ++nt) {
                    const uint32_t* pbh = &bh[nt >> 1][(nt & 1) * 2];
                    const uint32_t* pbl = &bl[nt >> 1][(nt & 1) * 2];
                    mma_bf16(acc[mt][nt], ah[mt], pbh);
                    mma_bf16(acc[mt][nt], ah[mt], pbl);
                    mma_bf16(acc[mt][nt], al[mt], pbh);
                }
            }
        }
        __syncthreads();   // all warps done with this stage before it is refilled
    }

    // ---- epilogue: acc + LoRA(t * B^T) * scale ----
    float* sBl = reinterpret_cast<float*>(smem);   // [BN][RANK]
    {
        const int id = *id_ptr;
        const float* Bl2 = Blora_base + (size_t)id * Ntot * RANK + (size_t)n0 * RANK;
        for (int i = tid; i < BN * RANK; i += 256) sBl[i] = Bl2[i];
    }
    __syncthreads();

#pragma unroll
    for (int mt = 0; mt < 4; ++mt) {
#pragma unroll
        for (int half = 0; half < 2; ++half) {
            const int row = m0 + wm * 64 + mt * 16 + (lane >> 2) + half * 8;
            const float4 tr = *reinterpret_cast<const float4*>(t_vec + (size_t)row * RANK);
#pragma unroll
            for (int nt = 0; nt < 4; ++nt) {
                const int coll = wn * 32 + nt * 8 + (lane & 3) * 2;  // local col in [0,BN)
                float v[2];
#pragma unroll
                for (int e = 0; e < 2; ++e) {
                    const float* b4 = sBl + (coll + e) * RANK;
                    float d = fmaf(tr.x, b4[0], fmaf(tr.y, b4[1],
                              fmaf(tr.z, b4[2], tr.w * b4[3])));
                    v[e] = acc[mt][nt][half * 2 + e] + LORA_SCALE * d;
                }
                const size_t o = (size_t)row * Ntot + n0 + coll;
                if (SPLIT_RELU) {
                    uint16_t hv[2], lv[2];
#pragma unroll
                    for (int e = 0; e < 2; ++e) {
                        float val = fmaxf(v[e], 0.0f);
                        __nv_bfloat16 h = __float2bfloat16(val);
                        float rem = val - __bfloat162float(h);
                        hv[e] = __bfloat16_as_ushort(h);
                        lv[e] = __bfloat16_as_ushort(__float2bfloat16(rem));
                    }
                    *reinterpret_cast<uint32_t*>(Oh + o) =
                        (uint32_t)hv[0] | ((uint32_t)hv[1] << 16);
                    *reinterpret_cast<uint32_t*>(Ol + o) =
                        (uint32_t)lv[0] | ((uint32_t)lv[1] << 16);
                } else {
                    *reinterpret_cast<float2*>(Of + o) = make_float2(v[0], v[1]);
                }
            }
        }
    }
}

// ---------------- fp32 -> bf16 hi/lo split ----------------
__global__ void split_kernel(const float* __restrict__ src,
                             __nv_bfloat16* __restrict__ hi,
                             __nv_bfloat16* __restrict__ lo, int n) {
    for (int i = blockIdx.x * blockDim.x + threadIdx.x; i < n; i += gridDim.x * blockDim.x) {
        float v = src[i];
        __nv_bfloat16 h = __float2bfloat16(v);
        float r = v - __bfloat162float(h);
        hi[i] = h;
        lo[i] = __float2bfloat16(r);
    }
}

// ---------------- t = X @ A[adapter]^T  (rank-4), fp32 X ----------------
__global__ void tvec_f32_kernel(const float* __restrict__ X, const float* __restrict__ Afull,
                                const int* __restrict__ idp, float* __restrict__ T, int K) {
    const int m = blockIdx.x;
    const int tid = threadIdx.x;
    const float* Aa = Afull + (size_t)(*idp) * RANK * K;
    const float* xr = X + (size_t)m * K;
    float s0 = 0.f, s1 = 0.f, s2 = 0.f, s3 = 0.f;
    for (int k = tid; k < K; k += 128) {
        float xv = xr[k];
        s0 += xv * Aa[k];
        s1 += xv * Aa[K + k];
        s2 += xv * Aa[2 * K + k];
        s3 += xv * Aa[3 * K + k];
    }
#pragma unroll
    for (int o = 16; o > 0; o >>= 1) {
        s0 += __shfl_xor_sync(0xffffffffu, s0, o);
        s1 += __shfl_xor_sync(0xffffffffu, s1, o);
        s2 += __shfl_xor_sync(0xffffffffu, s2, o);
        s3 += __shfl_xor_sync(0xffffffffu, s3, o);
    }
    __shared__ float red[4][4];
    const int wid = tid >> 5, lane = tid & 31;
    if (lane == 0) { red[wid][0] = s0; red[wid][1] = s1; red[wid][2] = s2; red[wid][3] = s3; }
    __syncthreads();
    if (tid < 4) T[(size_t)m * RANK + tid] = red[0][tid] + red[1][tid] + red[2][tid] + red[3][tid];
}

// ---------------- t = H @ A[adapter]^T with H = hi + lo (bf16 split) ----------------
__global__ void tvec_bf16_kernel(const __nv_bfloat16* __restrict__ Hh,
                                 const __nv_bfloat16* __restrict__ Hl,
                                 const float* __restrict__ Afull,
                                 const int* __restrict__ idp, float* __restrict__ T, int K) {
    const int m = blockIdx.x;
    const int tid = threadIdx.x;
    const float* Aa = Afull + (size_t)(*idp) * RANK * K;
    const size_t base = (size_t)m * K;
    float s0 = 0.f, s1 = 0.f, s2 = 0.f, s3 = 0.f;
    for (int k = tid; k < K; k += 128) {
        float xv = __bfloat162float(Hh[base + k]) + __bfloat162float(Hl[base + k]);
        s0 += xv * Aa[k];
        s1 += xv * Aa[K + k];
        s2 += xv * Aa[2 * K + k];
        s3 += xv * Aa[3 * K + k];
    }
#pragma unroll
    for (int o = 16; o > 0; o >>= 1) {
        s0 += __shfl_xor_sync(0xffffffffu, s0, o);
        s1 += __shfl_xor_sync(0xffffffffu, s1, o);
        s2 += __shfl_xor_sync(0xffffffffu, s2, o);
        s3 += __shfl_xor_sync(0xffffffffu, s3, o);
    }
    __shared__ float red[4][4];
    const int wid = tid >> 5, lane = tid & 31;
    if (lane == 0) { red[wid][0] = s0; red[wid][1] = s1; red[wid][2] = s2; red[wid][3] = s3; }
    __syncthreads();
    if (tid < 4) T[(size_t)m * RANK + tid] = red[0][tid] + red[1][tid] + red[2][tid] + red[3][tid];
}

// ---------------- launch ----------------
extern "C" void kernel_launch(void* const* d_in, const int* in_sizes, int n_in,
                              void* d_out, int out_size) {
    (void)in_sizes; (void)n_in; (void)out_size;
    const float* x  = (const float*)d_in[0];
    const float* W1 = (const float*)d_in[1];
    const float* A1 = (const float*)d_in[2];
    const float* B1 = (const float*)d_in[3];
    const float* W2 = (const float*)d_in[4];
    const float* A2 = (const float*)d_in[5];
    const float* B2 = (const float*)d_in[6];
    const int*   id = (const int*)d_in[7];
    float* out = (float*)d_out;

    __nv_bfloat16 *xh, *xl, *w1h, *w1l, *w2h, *w2l, *hh, *hl;
    float *t1, *t2;
    cudaGetSymbolAddress((void**)&xh,  g_xh);
    cudaGetSymbolAddress((void**)&xl,  g_xl);
    cudaGetSymbolAddress((void**)&w1h, g_w1h);
    cudaGetSymbolAddress((void**)&w1l, g_w1l);
    cudaGetSymbolAddress((void**)&w2h, g_w2h);
    cudaGetSymbolAddress((void**)&w2l, g_w2l);
    cudaGetSymbolAddress((void**)&hh,  g_hh);
    cudaGetSymbolAddress((void**)&hl,  g_hl);
    cudaGetSymbolAddress((void**)&t1,  g_t1);
    cudaGetSymbolAddress((void**)&t2,  g_t2);

    cudaFuncSetAttribute(gemm_hmma_kernel<true>,
                         cudaFuncAttributeMaxDynamicSharedMemorySize, SMEM_GEMM);
    cudaFuncSetAttribute(gemm_hmma_kernel<false>,
                         cudaFuncAttributeMaxDynamicSharedMemorySize, SMEM_GEMM);

    // split fp32 -> bf16 hi/lo
    split_kernel<<<4096, 256>>>(x,  xh,  xl,  M_TOK * NE);
    split_kernel<<<2048, 256>>>(W1, w1h, w1l, DFF * NE);
    split_kernel<<<2048, 256>>>(W2, w2h, w2l, NE * DFF);

    // t1 = x @ A1[id]^T
    tvec_f32_kernel<<<M_TOK, 128>>>(x, A1, id, t1, NE);

    // h = relu(x W1^T + t1 B1^T * s), stored as bf16 hi/lo
    gemm_hmma_kernel<true><<<dim3(DFF / BN, M_TOK / BM), 256, SMEM_GEMM>>>(
        xh, xl, w1h, w1l, NE, DFF, t1, B1, id, hh, hl, nullptr);

    // t2 = h @ A2[id]^T
    tvec_bf16_kernel<<<M_TOK, 128>>>(hh, hl, A2, id, t2, DFF);

    // out = h W2^T + t2 B2^T * s  (fp32)
    gemm_hmma_kernel<false><<<dim3(NE / BN, M_TOK / BM), 256, SMEM_GEMM>>>(
        hh, hl, w2h, w2l, DFF, NE, t2, B2, id, nullptr, nullptr, out);
}

// round 4
// speedup vs baseline: 1.3265x; 1.3265x over previous
#include <cuda_runtime.h>
#include <cuda_bf16.h>
#include <cuda_fp16.h>
#include <cstdint>

#define DEV_INLINE __device__ __forceinline__

// ---------------- problem dims (fixed by reference) ----------------
constexpr int M_TOK = 8 * 2048;   // 16384 tokens
constexpr int NE    = 1024;       // n_embd
constexpr int DFF   = 4096;       // 4*n_embd
constexpr int RANK  = 4;
constexpr float LORA_SCALE = 0.25f;

// ---------------- device scratch (allocation-free rule: __device__ globals) ----------------
__device__ __half g_xh[(size_t)M_TOK * NE];
__device__ __half g_xl[(size_t)M_TOK * NE];
__device__ __half g_w1f[(size_t)DFF * NE];
__device__ __half g_w2f[(size_t)NE * DFF];
__device__ __half g_hh[(size_t)M_TOK * DFF];
__device__ __half g_hl[(size_t)M_TOK * DFF];
__device__ __align__(16) float g_t1[(size_t)M_TOK * RANK];
__device__ __align__(16) float g_t2[(size_t)M_TOK * RANK];

// ---------------- PTX helpers (family-portable: cp.async, ldmatrix, mma.sync) ----------------
DEV_INLINE uint32_t smem_u32(const void* p) {
    uint32_t a;
    asm("{ .reg .u64 t; cvta.to.shared.u64 t, %1; cvt.u32.u64 %0, t; }" : "=r"(a) : "l"(p));
    return a;
}

#define CP_ASYNC16(dst, src) \
    asm volatile("cp.async.cg.shared.global [%0], [%1], 16;" :: "r"(dst), "l"(src))
#define CP_COMMIT() asm volatile("cp.async.commit_group;" ::: "memory")

template <int N>
DEV_INLINE void cp_wait() { asm volatile("cp.async.wait_group %0;" :: "n"(N) : "memory"); }

DEV_INLINE void ldsm_x4(uint32_t r[4], uint32_t addr) {
    asm volatile("ldmatrix.sync.aligned.m8n8.x4.shared.b16 {%0,%1,%2,%3}, [%4];"
                 : "=r"(r[0]), "=r"(r[1]), "=r"(r[2]), "=r"(r[3]) : "r"(addr));
}

DEV_INLINE void mma_f16(float c[4], const uint32_t a[4], const uint32_t* b) {
    asm volatile(
        "mma.sync.aligned.m16n8k16.row.col.f32.f16.f16.f32 "
        "{%0,%1,%2,%3}, {%4,%5,%6,%7}, {%8,%9}, {%0,%1,%2,%3};"
        : "+f"(c[0]), "+f"(c[1]), "+f"(c[2]), "+f"(c[3])
        : "r"(a[0]), "r"(a[1]), "r"(a[2]), "r"(a[3]), "r"(b[0]), "r"(b[1]));
}

// ---------------- GEMM config ----------------
// CTA tile 128x256, warp grid 2x4, warp tile 64x64, BK=64, 3 stages, fp16x2 split.
constexpr int BM = 128, BN = 256, BK = 64, STAGES = 3;
constexpr int ROWB     = BK * 2;                 // 128 bytes per swizzled row
constexpr int A_TILE_B = BM * ROWB;              // 16 KB
constexpr int B_TILE_B = BN * ROWB;              // 32 KB
constexpr int STAGE_B  = 2 * A_TILE_B + B_TILE_B;  // Axh, Axl, Bw = 64 KB
constexpr int SMEM_GEMM = STAGES * STAGE_B;      // 192 KB

// Load a ROWS x 64 fp16 tile into XOR-crosswise swizzled SMEM (16B granule c16 at
// column c16 ^ (row & 7)). Conflict-free for stores and ldmatrix.
template <int ROWS>
DEV_INLINE void load_tile(uint32_t sdst, const __half* g, int r0, int kc,
                          int ldK, int tid) {
    const char* gb = reinterpret_cast<const char*>(g);
#pragma unroll
    for (int i = 0; i < ROWS * 8 / 256; ++i) {
        int gidx = tid + i * 256;
        int row = gidx >> 3;
        int c16 = gidx & 7;
        uint32_t dst = sdst + row * ROWB + ((c16 ^ (row & 7)) << 4);
        const char* src = gb + ((size_t)(r0 + row) * ldK + kc + c16 * 8) * 2;
        CP_ASYNC16(dst, src);
    }
}

DEV_INLINE void load_stage(uint32_t s_stage,
                           const __half* Ah, const __half* Al, const __half* Bw,
                           int m0, int n0, int kc, int K, int tid) {
    load_tile<BM>(s_stage + 0 * A_TILE_B, Ah, m0, kc, K, tid);
    load_tile<BM>(s_stage + 1 * A_TILE_B, Al, m0, kc, K, tid);
    load_tile<BN>(s_stage + 2 * A_TILE_B, Bw, n0, kc, K, tid);
}

// ---------------- fused GEMM: D = A*B^T (fp16 hi/lo x fp16 W) + LoRA ----------------
// SPLIT_RELU ? (relu + write fp16 hi/lo pair) : (write fp32)
template <bool SPLIT_RELU>
__global__ void __launch_bounds__(256, 1)
gemm_hmma_kernel(const __half* __restrict__ Ah, const __half* __restrict__ Al,
                 const __half* __restrict__ Bw,
                 int K, int Ntot,
                 const float* __restrict__ t_vec,       // [M_TOK, RANK]
                 const float* __restrict__ Blora_base,  // [NUM_LOOPS, Ntot, RANK]
                 const int* __restrict__ id_ptr,
                 __half* __restrict__ Oh, __half* __restrict__ Ol,
                 float* __restrict__ Of) {
    extern __shared__ char smem[];
    const uint32_t sbase = smem_u32(smem);
    const int tid  = threadIdx.x;
    const int lane = tid & 31;
    const int warp = tid >> 5;
    const int wm = warp >> 2;   // 0..1 : warp m-tile (64 rows)
    const int wn = warp & 3;    // 0..3 : warp n-tile (64 cols)

    const int m0 = blockIdx.y * BM;
    const int n0 = blockIdx.x * BN;
    const int NC = K / BK;

    float acc[4][8][4];
#pragma unroll
    for (int i = 0; i < 4; ++i)
#pragma unroll
        for (int j = 0; j < 8; ++j)
#pragma unroll
            for (int e = 0; e < 4; ++e) acc[i][j][e] = 0.0f;

    // prologue: fill STAGES-1 stages
#pragma unroll
    for (int s = 0; s < STAGES - 1; ++s) {
        load_stage(sbase + s * STAGE_B, Ah, Al, Bw, m0, n0, s * BK, K, tid);
        CP_COMMIT();
    }

    // per-thread fragment address components (XOR swizzle)
    const int arow = wm * 64 + (lane & 15);                       // A: ldmatrix x4 rows
    const int brow = wn * 64 + ((lane >> 4) << 3) + (lane & 7);   // B: two n8 tiles per x4
    const int swA  = (lane & 15) & 7;
    const int swB  = lane & 7;

    for (int c = 0; c < NC; ++c) {
        const int pre = c + STAGES - 1;
        if (pre < NC) {
            load_stage(sbase + (pre % STAGES) * STAGE_B, Ah, Al, Bw,
                       m0, n0, pre * BK, K, tid);
            CP_COMMIT();
            cp_wait<STAGES - 1>();
        } else if (c == NC - 2) {
            cp_wait<1>();
        } else {
            cp_wait<0>();
        }
        __syncthreads();

        const uint32_t st   = sbase + (c % STAGES) * STAGE_B;
        const uint32_t stAh = st + 0 * A_TILE_B + arow * ROWB;
        const uint32_t stAl = st + 1 * A_TILE_B + arow * ROWB;
        const uint32_t stBw = st + 2 * A_TILE_B + brow * ROWB;

#pragma unroll
        for (int ks = 0; ks < 4; ++ks) {   // 4 x k16 per 64-K chunk
            const uint32_t axo = (uint32_t)(((ks * 2 + (lane >> 4)) ^ swA) << 4);
            const uint32_t bxo = (uint32_t)(((ks * 2 + ((lane >> 3) & 1)) ^ swB) << 4);

            uint32_t ah[4][4], al[4][4], bf[4][4];
#pragma unroll
            for (int mt = 0; mt < 4; ++mt) {
                ldsm_x4(ah[mt], stAh + mt * 16 * ROWB + axo);
                ldsm_x4(al[mt], stAl + mt * 16 * ROWB + axo);
            }
#pragma unroll
            for (int np = 0; np < 4; ++np) {
                ldsm_x4(bf[np], stBw + np * 16 * ROWB + bxo);
            }
#pragma unroll
            for (int mt = 0; mt < 4; ++mt) {
#pragma unroll
                for (int nt = 0; nt < 8; ++nt) {
                    const uint32_t* pb = &bf[nt >> 1][(nt & 1) * 2];
                    mma_f16(acc[mt][nt], ah[mt], pb);
                    mma_f16(acc[mt][nt], al[mt], pb);
                }
            }
        }
        __syncthreads();   // all warps done with this stage before it is refilled
    }

    // ---- epilogue: acc + LoRA(t * B^T) * scale ----
    float* sBl = reinterpret_cast<float*>(smem);   // [BN][RANK]
    {
        const int id = *id_ptr;
        const float* Bl2 = Blora_base + (size_t)id * Ntot * RANK + (size_t)n0 * RANK;
        for (int i = tid; i < BN * RANK; i += 256) sBl[i] = Bl2[i];
    }
    __syncthreads();

#pragma unroll
    for (int mt = 0; mt < 4; ++mt) {
#pragma unroll
        for (int half = 0; half < 2; ++half) {
            const int row = m0 + wm * 64 + mt * 16 + (lane >> 2) + half * 8;
            const float4 tr = *reinterpret_cast<const float4*>(t_vec + (size_t)row * RANK);
#pragma unroll
            for (int nt = 0; nt < 8; ++nt) {
                const int coll = wn * 64 + nt * 8 + (lane & 3) * 2;  // local col in [0,BN)
                float v[2];
#pragma unroll
                for (int e = 0; e < 2; ++e) {
                    const float* b4 = sBl + (coll + e) * RANK;
                    float d = fmaf(tr.x, b4[0], fmaf(tr.y, b4[1],
                              fmaf(tr.z, b4[2], tr.w * b4[3])));
                    v[e] = acc[mt][nt][half * 2 + e] + LORA_SCALE * d;
                }
                const size_t o = (size_t)row * Ntot + n0 + coll;
                if (SPLIT_RELU) {
                    uint16_t hv[2], lv[2];
#pragma unroll
                    for (int e = 0; e < 2; ++e) {
                        float val = fmaxf(v[e], 0.0f);
                        __half h = __float2half(val);
                        float rem = val - __half2float(h);
                        hv[e] = __half_as_ushort(h);
                        lv[e] = __half_as_ushort(__float2half(rem));
                    }
                    *reinterpret_cast<uint32_t*>(Oh + o) =
                        (uint32_t)hv[0] | ((uint32_t)hv[1] << 16);
                    *reinterpret_cast<uint32_t*>(Ol + o) =
                        (uint32_t)lv[0] | ((uint32_t)lv[1] << 16);
                } else {
                    *reinterpret_cast<float2*>(Of + o) = make_float2(v[0], v[1]);
                }
            }
        }
    }
}

// ---------------- fp32 -> fp16 hi/lo split ----------------
__global__ void split_kernel(const float* __restrict__ src,
                             __half* __restrict__ hi,
                             __half* __restrict__ lo, int n) {
    for (int i = blockIdx.x * blockDim.x + threadIdx.x; i < n; i += gridDim.x * blockDim.x) {
        float v = src[i];
        __half h = __float2half(v);
        float r = v - __half2float(h);
        hi[i] = h;
        lo[i] = __float2half(r);
    }
}

// ---------------- fp32 -> fp16 single convert ----------------
__global__ void cvt_kernel(const float* __restrict__ src, __half* __restrict__ dst, int n) {
    for (int i = blockIdx.x * blockDim.x + threadIdx.x; i < n; i += gridDim.x * blockDim.x) {
        dst[i] = __float2half(src[i]);
    }
}

// ---------------- t = X @ A[adapter]^T  (rank-4), fp32 X ----------------
__global__ void tvec_f32_kernel(const float* __restrict__ X, const float* __restrict__ Afull,
                                const int* __restrict__ idp, float* __restrict__ T, int K) {
    const int m = blockIdx.x;
    const int tid = threadIdx.x;
    const float* Aa = Afull + (size_t)(*idp) * RANK * K;
    const float* xr = X + (size_t)m * K;
    float s0 = 0.f, s1 = 0.f, s2 = 0.f, s3 = 0.f;
    for (int k = tid; k < K; k += 128) {
        float xv = xr[k];
        s0 += xv * Aa[k];
        s1 += xv * Aa[K + k];
        s2 += xv * Aa[2 * K + k];
        s3 += xv * Aa[3 * K + k];
    }
#pragma unroll
    for (int o = 16; o > 0; o >>= 1) {
        s0 += __shfl_xor_sync(0xffffffffu, s0, o);
        s1 += __shfl_xor_sync(0xffffffffu, s1, o);
        s2 += __shfl_xor_sync(0xffffffffu, s2, o);
        s3 += __shfl_xor_sync(0xffffffffu, s3, o);
    }
    __shared__ float red[4][4];
    const int wid = tid >> 5, lane = tid & 31;
    if (lane == 0) { red[wid][0] = s0; red[wid][1] = s1; red[wid][2] = s2; red[wid][3] = s3; }
    __syncthreads();
    if (tid < 4) T[(size_t)m * RANK + tid] = red[0][tid] + red[1][tid] + red[2][tid] + red[3][tid];
}

// ---------------- t = H @ A[adapter]^T with H = hi + lo (fp16 split) ----------------
__global__ void tvec_f16_kernel(const __half* __restrict__ Hh,
                                const __half* __restrict__ Hl,
                                const float* __restrict__ Afull,
                                const int* __restrict__ idp, float* __restrict__ T, int K) {
    const int m = blockIdx.x;
    const int tid = threadIdx.x;
    const float* Aa = Afull + (size_t)(*idp) * RANK * K;
    const size_t base = (size_t)m * K;
    float s0 = 0.f, s1 = 0.f, s2 = 0.f, s3 = 0.f;
    for (int k = tid; k < K; k += 128) {
        float xv = __half2float(Hh[base + k]) + __half2float(Hl[base + k]);
        s0 += xv * Aa[k];
        s1 += xv * Aa[K + k];
        s2 += xv * Aa[2 * K + k];
        s3 += xv * Aa[3 * K + k];
    }
#pragma unroll
    for (int o = 16; o > 0; o >>= 1) {
        s0 += __shfl_xor_sync(0xffffffffu, s0, o);
        s1 += __shfl_xor_sync(0xffffffffu, s1, o);
        s2 += __shfl_xor_sync(0xffffffffu, s2, o);
        s3 += __shfl_xor_sync(0xffffffffu, s3, o);
    }
    __shared__ float red[4][4];
    const int wid = tid >> 5, lane = tid & 31;
    if (lane == 0) { red[wid][0] = s0; red[wid][1] = s1; red[wid][2] = s2; red[wid][3] = s3; }
    __syncthreads();
    if (tid < 4) T[(size_t)m * RANK + tid] = red[0][tid] + red[1][tid] + red[2][tid] + red[3][tid];
}

// ---------------- launch ----------------
extern "C" void kernel_launch(void* const* d_in, const int* in_sizes, int n_in,
                              void* d_out, int out_size) {
    (void)in_sizes; (void)n_in; (void)out_size;
    const float* x  = (const float*)d_in[0];
    const float* W1 = (const float*)d_in[1];
    const float* A1 = (const float*)d_in[2];
    const float* B1 = (const float*)d_in[3];
    const float* W2 = (const float*)d_in[4];
    const float* A2 = (const float*)d_in[5];
    const float* B2 = (const float*)d_in[6];
    const int*   id = (const int*)d_in[7];
    float* out = (float*)d_out;

    __half *xh, *xl, *w1f, *w2f, *hh, *hl;
    float *t1, *t2;
    cudaGetSymbolAddress((void**)&xh,  g_xh);
    cudaGetSymbolAddress((void**)&xl,  g_xl);
    cudaGetSymbolAddress((void**)&w1f, g_w1f);
    cudaGetSymbolAddress((void**)&w2f, g_w2f);
    cudaGetSymbolAddress((void**)&hh,  g_hh);
    cudaGetSymbolAddress((void**)&hl,  g_hl);
    cudaGetSymbolAddress((void**)&t1,  g_t1);
    cudaGetSymbolAddress((void**)&t2,  g_t2);

    cudaFuncSetAttribute(gemm_hmma_kernel<true>,
                         cudaFuncAttributeMaxDynamicSharedMemorySize, SMEM_GEMM);
    cudaFuncSetAttribute(gemm_hmma_kernel<false>,
                         cudaFuncAttributeMaxDynamicSharedMemorySize, SMEM_GEMM);

    // precision prep
    split_kernel<<<4096, 256>>>(x, xh, xl, M_TOK * NE);
    cvt_kernel<<<2048, 256>>>(W1, w1f, DFF * NE);
    cvt_kernel<<<2048, 256>>>(W2, w2f, NE * DFF);

    // t1 = x @ A1[id]^T
    tvec_f32_kernel<<<M_TOK, 128>>>(x, A1, id, t1, NE);

    // h = relu(x W1^T + t1 B1^T * s), stored as fp16 hi/lo
    gemm_hmma_kernel<true><<<dim3(DFF / BN, M_TOK / BM), 256, SMEM_GEMM>>>(
        xh, xl, w1f, NE, DFF, t1, B1, id, hh, hl, nullptr);

    // t2 = h @ A2[id]^T
    tvec_f16_kernel<<<M_TOK, 128>>>(hh, hl, A2, id, t2, DFF);

    // out = h W2^T + t2 B2^T * s  (fp32)
    gemm_hmma_kernel<false><<<dim3(NE / BN, M_TOK / BM), 256, SMEM_GEMM>>>(
        hh, hl, w2f, DFF, NE, t2, B2, id, nullptr, nullptr, out);
}

// round 8
// speedup vs baseline: 2.3104x; 1.7417x over previous
#include <cuda_runtime.h>
#include <cuda_bf16.h>
#include <cuda_fp16.h>
#include <cstdint>

#define DEV_INLINE __device__ __forceinline__

// ---------------- problem dims (fixed by reference) ----------------
constexpr int M_TOK = 8 * 2048;   // 16384 tokens
constexpr int NE    = 1024;       // n_embd
constexpr int DFF   = 4096;       // 4*n_embd
constexpr int RANK  = 4;
constexpr float LORA_SCALE = 0.25f;

// ---------------- device scratch (allocation-free rule: __device__ globals) ----------------
__device__ __half g_xf[(size_t)M_TOK * NE];
__device__ __half g_w1f[(size_t)DFF * NE];
__device__ __half g_w2f[(size_t)NE * DFF];
__device__ __half g_hf[(size_t)M_TOK * DFF];
__device__ __align__(16) float g_t1[(size_t)M_TOK * RANK];
__device__ __align__(16) float g_t2[(size_t)M_TOK * RANK];

// ---------------- PTX helpers (family-portable: cp.async, ldmatrix, mma.sync) ----------------
DEV_INLINE uint32_t smem_u32(const void* p) {
    uint32_t a;
    asm("{ .reg .u64 t; cvta.to.shared.u64 t, %1; cvt.u32.u64 %0, t; }" : "=r"(a) : "l"(p));
    return a;
}

#define CP_ASYNC16(dst, src) \
    asm volatile("cp.async.cg.shared.global [%0], [%1], 16;" :: "r"(dst), "l"(src))
#define CP_COMMIT() asm volatile("cp.async.commit_group;" ::: "memory")

template <int N>
DEV_INLINE void cp_wait() { asm volatile("cp.async.wait_group %0;" :: "n"(N) : "memory"); }

DEV_INLINE void ldsm_x4(uint32_t r[4], uint32_t addr) {
    asm volatile("ldmatrix.sync.aligned.m8n8.x4.shared.b16 {%0,%1,%2,%3}, [%4];"
                 : "=r"(r[0]), "=r"(r[1]), "=r"(r[2]), "=r"(r[3]) : "r"(addr));
}

DEV_INLINE void mma_f16(float c[4], const uint32_t a[4], const uint32_t* b) {
    asm volatile(
        "mma.sync.aligned.m16n8k16.row.col.f32.f16.f16.f32 "
        "{%0,%1,%2,%3}, {%4,%5,%6,%7}, {%8,%9}, {%0,%1,%2,%3};"
        : "+f"(c[0]), "+f"(c[1]), "+f"(c[2]), "+f"(c[3])
        : "r"(a[0]), "r"(a[1]), "r"(a[2]), "r"(a[3]), "r"(b[0]), "r"(b[1]));
}

// ---------------- GEMM config ----------------
// CTA tile 128x256, warp grid 2x4, warp tile 64x64, BK=64, 4 stages, pure fp16.
constexpr int BM = 128, BN = 256, BK = 64, STAGES = 4;
constexpr int ROWB     = BK * 2;                 // 128 bytes per swizzled row
constexpr int A_TILE_B = BM * ROWB;              // 16 KB
constexpr int B_TILE_B = BN * ROWB;              // 32 KB
constexpr int STAGE_B  = A_TILE_B + B_TILE_B;    // 48 KB
constexpr int SMEM_GEMM = STAGES * STAGE_B;      // 192 KB

// Load a ROWS x 64 fp16 tile into XOR-crosswise swizzled SMEM (16B granule c16 at
// column c16 ^ (row & 7)). Conflict-free for stores and ldmatrix.
template <int ROWS>
DEV_INLINE void load_tile(uint32_t sdst, const __half* g, int r0, int kc,
                          int ldK, int tid) {
    const char* gb = reinterpret_cast<const char*>(g);
#pragma unroll
    for (int i = 0; i < ROWS * 8 / 256; ++i) {
        int gidx = tid + i * 256;
        int row = gidx >> 3;
        int c16 = gidx & 7;
        uint32_t dst = sdst + row * ROWB + ((c16 ^ (row & 7)) << 4);
        const char* src = gb + ((size_t)(r0 + row) * ldK + kc + c16 * 8) * 2;
        CP_ASYNC16(dst, src);
    }
}

DEV_INLINE void load_stage(uint32_t s_stage,
                           const __half* A, const __half* Bw,
                           int m0, int n0, int kc, int K, int tid) {
    load_tile<BM>(s_stage, A, m0, kc, K, tid);
    load_tile<BN>(s_stage + A_TILE_B, Bw, n0, kc, K, tid);
}

// ---------------- fused GEMM: D = A*B^T (fp16) + LoRA ----------------
// RELU_F16 ? (relu + write fp16) : (write fp32)
template <bool RELU_F16>
__global__ void __launch_bounds__(256, 1)
gemm_hmma_kernel(const __half* __restrict__ A, const __half* __restrict__ Bw,
                 int K, int Ntot,
                 const float* __restrict__ t_vec,       // [M_TOK, RANK]
                 const float* __restrict__ Blora_base,  // [NUM_LOOPS, Ntot, RANK]
                 const int* __restrict__ id_ptr,
                 __half* __restrict__ Oh, float* __restrict__ Of) {
    extern __shared__ char smem[];
    const uint32_t sbase = smem_u32(smem);
    const int tid  = threadIdx.x;
    const int lane = tid & 31;
    const int warp = tid >> 5;
    const int wm = warp >> 2;   // 0..1 : warp m-tile (64 rows)
    const int wn = warp & 3;    // 0..3 : warp n-tile (64 cols)

    const int m0 = blockIdx.y * BM;
    const int n0 = blockIdx.x * BN;
    const int NC = K / BK;

    float acc[4][8][4];
#pragma unroll
    for (int i = 0; i < 4; ++i)
#pragma unroll
        for (int j = 0; j < 8; ++j)
#pragma unroll
            for (int e = 0; e < 4; ++e) acc[i][j][e] = 0.0f;

    // prologue: fill STAGES-1 stages
#pragma unroll
    for (int s = 0; s < STAGES - 1; ++s) {
        load_stage(sbase + s * STAGE_B, A, Bw, m0, n0, s * BK, K, tid);
        CP_COMMIT();
    }

    // per-thread fragment address components (XOR swizzle)
    const int arow = wm * 64 + (lane & 15);                       // A: ldmatrix x4 rows
    const int brow = wn * 64 + ((lane >> 4) << 3) + (lane & 7);   // B: two n8 tiles per x4
    const int swA  = (lane & 15) & 7;
    const int swB  = lane & 7;

    for (int c = 0; c < NC; ++c) {
        const int pre = c + STAGES - 1;
        if (pre < NC) {
            load_stage(sbase + (pre % STAGES) * STAGE_B, A, Bw, m0, n0, pre * BK, K, tid);
            CP_COMMIT();
            cp_wait<STAGES - 1>();
        } else {
            const int rem = NC - 1 - c;
            if (rem >= 2) { cp_wait<2>(); }
            else if (rem == 1) { cp_wait<1>(); }
            else { cp_wait<0>(); }
        }
        __syncthreads();

        const uint32_t st  = sbase + (c % STAGES) * STAGE_B;
        const uint32_t stA = st + arow * ROWB;
        const uint32_t stB = st + A_TILE_B + brow * ROWB;

#pragma unroll
        for (int ks = 0; ks < 4; ++ks) {   // 4 x k16 per 64-K chunk
            const uint32_t axo = (uint32_t)(((ks * 2 + (lane >> 4)) ^ swA) << 4);
            const uint32_t bxo = (uint32_t)(((ks * 2 + ((lane >> 3) & 1)) ^ swB) << 4);

            uint32_t af[4][4], bf[4][4];
#pragma unroll
            for (int mt = 0; mt < 4; ++mt) ldsm_x4(af[mt], stA + mt * 16 * ROWB + axo);
#pragma unroll
            for (int np = 0; np < 4; ++np) ldsm_x4(bf[np], stB + np * 16 * ROWB + bxo);

#pragma unroll
            for (int mt = 0; mt < 4; ++mt) {
#pragma unroll
                for (int nt = 0; nt < 8; ++nt) {
                    mma_f16(acc[mt][nt], af[mt], &bf[nt >> 1][(nt & 1) * 2]);
                }
            }
        }
        __syncthreads();   // all warps done with this stage before it is refilled
    }

    // ---- epilogue: acc + LoRA(t * B^T) * scale ----
    float* sBl = reinterpret_cast<float*>(smem);   // [BN][RANK]
    {
        const int id = *id_ptr;
        const float* Bl2 = Blora_base + (size_t)id * Ntot * RANK + (size_t)n0 * RANK;
        for (int i = tid; i < BN * RANK; i += 256) sBl[i] = Bl2[i];
    }
    __syncthreads();

#pragma unroll
    for (int mt = 0; mt < 4; ++mt) {
#pragma unroll
        for (int half = 0; half < 2; ++half) {
            const int row = m0 + wm * 64 + mt * 16 + (lane >> 2) + half * 8;
            const float4 tr = *reinterpret_cast<const float4*>(t_vec + (size_t)row * RANK);
#pragma unroll
            for (int nt = 0; nt < 8; ++nt) {
                const int coll = wn * 64 + nt * 8 + (lane & 3) * 2;  // local col in [0,BN)
                float v[2];
#pragma unroll
                for (int e = 0; e < 2; ++e) {
                    const float* b4 = sBl + (coll + e) * RANK;
                    float d = fmaf(tr.x, b4[0], fmaf(tr.y, b4[1],
                              fmaf(tr.z, b4[2], tr.w * b4[3])));
                    v[e] = acc[mt][nt][half * 2 + e] + LORA_SCALE * d;
                }
                const size_t o = (size_t)row * Ntot + n0 + coll;
                if (RELU_F16) {
                    __half2 hv;
                    hv.x = __float2half(fmaxf(v[0], 0.0f));
                    hv.y = __float2half(fmaxf(v[1], 0.0f));
                    *reinterpret_cast<__half2*>(Oh + o) = hv;
                } else {
                    *reinterpret_cast<float2*>(Of + o) = make_float2(v[0], v[1]);
                }
            }
        }
    }
}

// ---------------- fp32 -> fp16 convert ----------------
__global__ void cvt_kernel(const float* __restrict__ src, __half* __restrict__ dst, int n) {
    int i = blockIdx.x * blockDim.x + threadIdx.x;
    const int stride = gridDim.x * blockDim.x;
    for (; i * 4 + 3 < n; i += stride) {
        float4 v = *reinterpret_cast<const float4*>(src + i * 4);
        __half2 a = __floats2half2_rn(v.x, v.y);
        __half2 b = __floats2half2_rn(v.z, v.w);
        *reinterpret_cast<uint2*>(dst + i * 4) =
            make_uint2(*reinterpret_cast<uint32_t*>(&a), *reinterpret_cast<uint32_t*>(&b));
    }
}

// ---------------- t = X @ A[adapter]^T  (rank-4), fp32 X ----------------
__global__ void tvec_f32_kernel(const float* __restrict__ X, const float* __restrict__ Afull,
                                const int* __restrict__ idp, float* __restrict__ T, int K) {
    const int m = blockIdx.x;
    const int tid = threadIdx.x;
    const float* Aa = Afull + (size_t)(*idp) * RANK * K;
    const float* xr = X + (size_t)m * K;
    float s0 = 0.f, s1 = 0.f, s2 = 0.f, s3 = 0.f;
    for (int k = tid; k < K; k += 128) {
        float xv = xr[k];
        s0 += xv * Aa[k];
        s1 += xv * Aa[K + k];
        s2 += xv * Aa[2 * K + k];
        s3 += xv * Aa[3 * K + k];
    }
#pragma unroll
    for (int o = 16; o > 0; o >>= 1) {
        s0 += __shfl_xor_sync(0xffffffffu, s0, o);
        s1 += __shfl_xor_sync(0xffffffffu, s1, o);
        s2 += __shfl_xor_sync(0xffffffffu, s2, o);
        s3 += __shfl_xor_sync(0xffffffffu, s3, o);
    }
    __shared__ float red[4][4];
    const int wid = tid >> 5, lane = tid & 31;
    if (lane == 0) { red[wid][0] = s0; red[wid][1] = s1; red[wid][2] = s2; red[wid][3] = s3; }
    __syncthreads();
    if (tid < 4) T[(size_t)m * RANK + tid] = red[0][tid] + red[1][tid] + red[2][tid] + red[3][tid];
}

// ---------------- t = H @ A[adapter]^T (fp16 H) ----------------
__global__ void tvec_f16_kernel(const __half* __restrict__ H,
                                const float* __restrict__ Afull,
                                const int* __restrict__ idp, float* __restrict__ T, int K) {
    const int m = blockIdx.x;
    const int tid = threadIdx.x;
    const float* Aa = Afull + (size_t)(*idp) * RANK * K;
    const size_t base = (size_t)m * K;
    float s0 = 0.f, s1 = 0.f, s2 = 0.f, s3 = 0.f;
    for (int k = tid; k < K; k += 128) {
        float xv = __half2float(H[base + k]);
        s0 += xv * Aa[k];
        s1 += xv * Aa[K + k];
        s2 += xv * Aa[2 * K + k];
        s3 += xv * Aa[3 * K + k];
    }
#pragma unroll
    for (int o = 16; o > 0; o >>= 1) {
        s0 += __shfl_xor_sync(0xffffffffu, s0, o);
        s1 += __shfl_xor_sync(0xffffffffu, s1, o);
        s2 += __shfl_xor_sync(0xffffffffu, s2, o);
        s3 += __shfl_xor_sync(0xffffffffu, s3, o);
    }
    __shared__ float red[4][4];
    const int wid = tid >> 5, lane = tid & 31;
    if (lane == 0) { red[wid][0] = s0; red[wid][1] = s1; red[wid][2] = s2; red[wid][3] = s3; }
    __syncthreads();
    if (tid < 4) T[(size_t)m * RANK + tid] = red[0][tid] + red[1][tid] + red[2][tid] + red[3][tid];
}

// ---------------- launch ----------------
extern "C" void kernel_launch(void* const* d_in, const int* in_sizes, int n_in,
                              void* d_out, int out_size) {
    (void)in_sizes; (void)n_in; (void)out_size;
    const float* x  = (const float*)d_in[0];
    const float* W1 = (const float*)d_in[1];
    const float* A1 = (const float*)d_in[2];
    const float* B1 = (const float*)d_in[3];
    const float* W2 = (const float*)d_in[4];
    const float* A2 = (const float*)d_in[5];
    const float* B2 = (const float*)d_in[6];
    const int*   id = (const int*)d_in[7];
    float* out = (float*)d_out;

    __half *xf, *w1f, *w2f, *hf;
    float *t1, *t2;
    cudaGetSymbolAddress((void**)&xf,  g_xf);
    cudaGetSymbolAddress((void**)&w1f, g_w1f);
    cudaGetSymbolAddress((void**)&w2f, g_w2f);
    cudaGetSymbolAddress((void**)&hf,  g_hf);
    cudaGetSymbolAddress((void**)&t1,  g_t1);
    cudaGetSymbolAddress((void**)&t2,  g_t2);

    cudaFuncSetAttribute(gemm_hmma_kernel<true>,
                         cudaFuncAttributeMaxDynamicSharedMemorySize, SMEM_GEMM);
    cudaFuncSetAttribute(gemm_hmma_kernel<false>,
                         cudaFuncAttributeMaxDynamicSharedMemorySize, SMEM_GEMM);

    // precision prep
    cvt_kernel<<<2048, 256>>>(x,  xf,  M_TOK * NE);
    cvt_kernel<<<2048, 256>>>(W1, w1f, DFF * NE);
    cvt_kernel<<<2048, 256>>>(W2, w2f, NE * DFF);

    // t1 = x @ A1[id]^T   (fp32 x for accuracy)
    tvec_f32_kernel<<<M_TOK, 128>>>(x, A1, id, t1, NE);

    // h = relu(x W1^T + t1 B1^T * s), stored fp16
    gemm_hmma_kernel<true><<<dim3(DFF / BN, M_TOK / BM), 256, SMEM_GEMM>>>(
        xf, w1f, NE, DFF, t1, B1, id, hf, nullptr);

    // t2 = h @ A2[id]^T
    tvec_f16_kernel<<<M_TOK, 128>>>(hf, A2, id, t2, DFF);

    // out = h W2^T + t2 B2^T * s  (fp32)
    gemm_hmma_kernel<false><<<dim3(NE / BN, M_TOK / BM), 256, SMEM_GEMM>>>(
        hf, w2f, DFF, NE, t2, B2, id, nullptr, out);
}

// round 11
// speedup vs baseline: 2.5385x; 1.0987x over previous
#include <cuda_runtime.h>
#include <cuda_bf16.h>
#include <cuda_fp16.h>
#include <cstdint>

#define DEV_INLINE __device__ __forceinline__

// ---------------- problem dims (fixed by reference) ----------------
constexpr int M_TOK = 8 * 2048;   // 16384 tokens
constexpr int NE    = 1024;       // n_embd
constexpr int DFF   = 4096;       // 4*n_embd
constexpr int RANK  = 4;
constexpr float LORA_SCALE = 0.25f;

// ---------------- device scratch (allocation-free rule: __device__ globals) ----------------
__device__ __half g_xf[(size_t)M_TOK * NE];
__device__ __half g_w1f[(size_t)DFF * NE];
__device__ __half g_w2f[(size_t)NE * DFF];
__device__ __half g_hf[(size_t)M_TOK * DFF];
__device__ __align__(16) float g_t1[(size_t)M_TOK * RANK];
__device__ __align__(16) float g_t2[(size_t)M_TOK * RANK];

// ---------------- PTX helpers (family-portable: cp.async, ldmatrix, mma.sync) ----------------
DEV_INLINE uint32_t smem_u32(const void* p) {
    uint32_t a;
    asm("{ .reg .u64 t; cvta.to.shared.u64 t, %1; cvt.u32.u64 %0, t; }" : "=r"(a) : "l"(p));
    return a;
}

#define CP_ASYNC16(dst, src) \
    asm volatile("cp.async.cg.shared.global [%0], [%1], 16;" :: "r"(dst), "l"(src))
#define CP_COMMIT() asm volatile("cp.async.commit_group;" ::: "memory")

template <int N>
DEV_INLINE void cp_wait() { asm volatile("cp.async.wait_group %0;" :: "n"(N) : "memory"); }

DEV_INLINE void cp_wait_dyn(int w) {
    switch (w) {
        case 0: cp_wait<0>(); break;
        case 1: cp_wait<1>(); break;
        case 2: cp_wait<2>(); break;
        case 3: cp_wait<3>(); break;
        default: cp_wait<4>(); break;
    }
}

DEV_INLINE void ldsm_x4(uint32_t r[4], uint32_t addr) {
    asm volatile("ldmatrix.sync.aligned.m8n8.x4.shared.b16 {%0,%1,%2,%3}, [%4];"
                 : "=r"(r[0]), "=r"(r[1]), "=r"(r[2]), "=r"(r[3]) : "r"(addr));
}

DEV_INLINE void mma_f16(float c[4], const uint32_t a[4], const uint32_t* b) {
    asm volatile(
        "mma.sync.aligned.m16n8k16.row.col.f32.f16.f16.f32 "
        "{%0,%1,%2,%3}, {%4,%5,%6,%7}, {%8,%9}, {%0,%1,%2,%3};"
        : "+f"(c[0]), "+f"(c[1]), "+f"(c[2]), "+f"(c[3])
        : "r"(a[0]), "r"(a[1]), "r"(a[2]), "r"(a[3]), "r"(b[0]), "r"(b[1]));
}

// ---------------- GEMM config ----------------
// CTA tile 128 x BN_T, warp grid 2x4, warp tile 64 x (BN_T/4), BK=64, pure fp16.
constexpr int BM = 128, BK = 64;
constexpr int ROWB     = BK * 2;                 // 128 bytes per swizzled row
constexpr int A_TILE_B = BM * ROWB;              // 16 KB
constexpr int SMEM_GEMM = 192 * 1024;            // both variants use 192 KB

// Load a ROWS x 64 fp16 tile into XOR-crosswise swizzled SMEM (16B granule c16 at
// column c16 ^ (row & 7)). Conflict-free for stores and ldmatrix.
template <int ROWS>
DEV_INLINE void load_tile(uint32_t sdst, const __half* g, int r0, int kc,
                          int ldK, int tid) {
    const char* gb = reinterpret_cast<const char*>(g);
#pragma unroll
    for (int i = 0; i < ROWS * 8 / 256; ++i) {
        int gidx = tid + i * 256;
        int row = gidx >> 3;
        int c16 = gidx & 7;
        uint32_t dst = sdst + row * ROWB + ((c16 ^ (row & 7)) << 4);
        const char* src = gb + ((size_t)(r0 + row) * ldK + kc + c16 * 8) * 2;
        CP_ASYNC16(dst, src);
    }
}

// ---------------- fused GEMM: D = A*B^T (fp16) + LoRA ----------------
// RELU_F16 ? (relu + write fp16) : (write fp32)
template <int BN_T, int STAGES_T, bool RELU_F16>
__global__ void __launch_bounds__(256, 1)
gemm_hmma_kernel(const __half* __restrict__ A, const __half* __restrict__ Bw,
                 int K, int Ntot,
                 const float* __restrict__ t_vec,       // [M_TOK, RANK]
                 const float* __restrict__ Blora_base,  // [NUM_LOOPS, Ntot, RANK]
                 const int* __restrict__ id_ptr,
                 __half* __restrict__ Oh, float* __restrict__ Of) {
    constexpr int NT  = BN_T / 32;        // n8-tile count per warp (warp n = BN_T/4)
    constexpr int NPB = NT / 2;           // B ldmatrix-x4 count
    constexpr int B_TILE_BT = BN_T * ROWB;
    constexpr int STAGE_BT  = A_TILE_B + B_TILE_BT;

    extern __shared__ char smem[];
    const uint32_t sbase = smem_u32(smem);
    const int tid  = threadIdx.x;
    const int lane = tid & 31;
    const int warp = tid >> 5;
    const int wm = warp >> 2;   // 0..1 : warp m-tile (64 rows)
    const int wn = warp & 3;    // 0..3 : warp n-tile (BN_T/4 cols)

    const int m0 = blockIdx.y * BM;
    const int n0 = blockIdx.x * BN_T;
    const int NC = K / BK;

    float acc[4][NT][4];
#pragma unroll
    for (int i = 0; i < 4; ++i)
#pragma unroll
        for (int j = 0; j < NT; ++j)
#pragma unroll
            for (int e = 0; e < 4; ++e) acc[i][j][e] = 0.0f;

    // prologue: fill STAGES_T-1 stages
#pragma unroll
    for (int s = 0; s < STAGES_T - 1; ++s) {
        load_tile<BM>(sbase + s * STAGE_BT, A, m0, s * BK, K, tid);
        load_tile<BN_T>(sbase + s * STAGE_BT + A_TILE_B, Bw, n0, s * BK, K, tid);
        CP_COMMIT();
    }

    // per-thread fragment address components (XOR swizzle)
    const int arow = wm * 64 + (lane & 15);                             // A rows
    const int brow = wn * (BN_T / 4) + ((lane >> 4) << 3) + (lane & 7); // B rows
    const int swA  = (lane & 15) & 7;
    const int swB  = lane & 7;

    for (int c = 0; c < NC; ++c) {
        // wait until chunk c's group is complete (steady state: STAGES_T-2 newer in flight)
        const int rem = NC - 1 - c;
        if (rem >= STAGES_T - 2) { cp_wait<STAGES_T - 2>(); }
        else                     { cp_wait_dyn(rem); }
        __syncthreads();   // single barrier per chunk: data visible AND all warps
                           // finished chunk c-1 (protects the refill below)

        const uint32_t st  = sbase + (c % STAGES_T) * STAGE_BT;
        const uint32_t stA = st + arow * ROWB;
        const uint32_t stB = st + A_TILE_B + brow * ROWB;

#pragma unroll
        for (int ks = 0; ks < 4; ++ks) {   // 4 x k16 per 64-K chunk
            const uint32_t axo = (uint32_t)(((ks * 2 + (lane >> 4)) ^ swA) << 4);
            const uint32_t bxo = (uint32_t)(((ks * 2 + ((lane >> 3) & 1)) ^ swB) << 4);

            uint32_t af[4][4], bf[NPB][4];
#pragma unroll
            for (int mt = 0; mt < 4; ++mt) ldsm_x4(af[mt], stA + mt * 16 * ROWB + axo);
#pragma unroll
            for (int np = 0; np < NPB; ++np) ldsm_x4(bf[np], stB + np * 16 * ROWB + bxo);

#pragma unroll
            for (int mt = 0; mt < 4; ++mt) {
#pragma unroll
                for (int nt = 0; nt < NT; ++nt) {
                    mma_f16(acc[mt][nt], af[mt], &bf[nt >> 1][(nt & 1) * 2]);
                }
            }
        }

        // refill: stage (c+S-1)%S == (c-1)%S, consumed at iter c-1; every warp
        // passed this iteration's barrier after finishing iter c-1 -> safe.
        const int pre = c + STAGES_T - 1;
        if (pre < NC) {
            const uint32_t sp = sbase + (pre % STAGES_T) * STAGE_BT;
            load_tile<BM>(sp, A, m0, pre * BK, K, tid);
            load_tile<BN_T>(sp + A_TILE_B, Bw, n0, pre * BK, K, tid);
            CP_COMMIT();
        }
    }

    // ---- epilogue: acc + LoRA(t * B^T) * scale ----
    // sBl lives in stage-0 region; last chunks never map to stage 0 here
    // (NC-1 mod STAGES_T != 0 for both instantiations) and warp skew < 1 iter.
    float* sBl = reinterpret_cast<float*>(smem);   // [BN_T][RANK]
    {
        const int id = *id_ptr;
        const float* Bl2 = Blora_base + (size_t)id * Ntot * RANK + (size_t)n0 * RANK;
        for (int i = tid; i < BN_T * RANK; i += 256) sBl[i] = Bl2[i];
    }
    __syncthreads();

#pragma unroll
    for (int mt = 0; mt < 4; ++mt) {
#pragma unroll
        for (int half = 0; half < 2; ++half) {
            const int row = m0 + wm * 64 + mt * 16 + (lane >> 2) + half * 8;
            const float4 tr = *reinterpret_cast<const float4*>(t_vec + (size_t)row * RANK);
#pragma unroll
            for (int nt = 0; nt < NT; ++nt) {
                const int coll = wn * (BN_T / 4) + nt * 8 + (lane & 3) * 2;
                float v[2];
#pragma unroll
                for (int e = 0; e < 2; ++e) {
                    const float* b4 = sBl + (coll + e) * RANK;
                    float d = fmaf(tr.x, b4[0], fmaf(tr.y, b4[1],
                              fmaf(tr.z, b4[2], tr.w * b4[3])));
                    v[e] = acc[mt][nt][half * 2 + e] + LORA_SCALE * d;
                }
                const size_t o = (size_t)row * Ntot + n0 + coll;
                if (RELU_F16) {
                    __half2 hv;
                    hv.x = __float2half(fmaxf(v[0], 0.0f));
                    hv.y = __float2half(fmaxf(v[1], 0.0f));
                    *reinterpret_cast<__half2*>(Oh + o) = hv;
                } else {
                    *reinterpret_cast<float2*>(Of + o) = make_float2(v[0], v[1]);
                }
            }
        }
    }
}

// ---------------- fp32 -> fp16 convert (for weights) ----------------
__global__ void cvt_kernel(const float* __restrict__ src, __half* __restrict__ dst, int n) {
    int i = blockIdx.x * blockDim.x + threadIdx.x;
    const int stride = gridDim.x * blockDim.x;
    for (; i * 4 + 3 < n; i += stride) {
        float4 v = *reinterpret_cast<const float4*>(src + i * 4);
        __half2 a = __floats2half2_rn(v.x, v.y);
        __half2 b = __floats2half2_rn(v.z, v.w);
        *reinterpret_cast<uint2*>(dst + i * 4) =
            make_uint2(*reinterpret_cast<uint32_t*>(&a), *reinterpret_cast<uint32_t*>(&b));
    }
}

// ---------------- fused: t1 = x @ A1[id]^T AND xf = fp16(x). One block per row. ----------------
__global__ void __launch_bounds__(128)
tvec_x_kernel(const float* __restrict__ X, const float* __restrict__ Afull,
              const int* __restrict__ idp, float* __restrict__ T,
              __half* __restrict__ Xf) {
    const int m = blockIdx.x;
    const int tid = threadIdx.x;
    const float* Aa = Afull + (size_t)(*idp) * RANK * NE;
    const float* xr = X + (size_t)m * NE + tid * 8;     // 8 contiguous floats/thread

    float4 v0 = *reinterpret_cast<const float4*>(xr);
    float4 v1 = *reinterpret_cast<const float4*>(xr + 4);

    // fp16 store (coalesced 16B per thread)
    {
        __half2 a = __floats2half2_rn(v0.x, v0.y);
        __half2 b = __floats2half2_rn(v0.z, v0.w);
        __half2 cc = __floats2half2_rn(v1.x, v1.y);
        __half2 dd = __floats2half2_rn(v1.z, v1.w);
        *reinterpret_cast<uint4*>(Xf + (size_t)m * NE + tid * 8) =
            make_uint4(*reinterpret_cast<uint32_t*>(&a), *reinterpret_cast<uint32_t*>(&b),
                       *reinterpret_cast<uint32_t*>(&cc), *reinterpret_cast<uint32_t*>(&dd));
    }

    float s[4];
#pragma unroll
    for (int r = 0; r < RANK; ++r) {
        const float* ar = Aa + (size_t)r * NE + tid * 8;
        float4 a0 = *reinterpret_cast<const float4*>(ar);
        float4 a1 = *reinterpret_cast<const float4*>(ar + 4);
        s[r] = v0.x * a0.x + v0.y * a0.y + v0.z * a0.z + v0.w * a0.w
             + v1.x * a1.x + v1.y * a1.y + v1.z * a1.z + v1.w * a1.w;
    }
#pragma unroll
    for (int o = 16; o > 0; o >>= 1) {
#pragma unroll
        for (int r = 0; r < RANK; ++r) s[r] += __shfl_xor_sync(0xffffffffu, s[r], o);
    }
    __shared__ float red[4][4];
    const int wid = tid >> 5, lane = tid & 31;
    if (lane == 0) {
#pragma unroll
        for (int r = 0; r < RANK; ++r) red[wid][r] = s[r];
    }
    __syncthreads();
    if (tid < 4) T[(size_t)m * RANK + tid] = red[0][tid] + red[1][tid] + red[2][tid] + red[3][tid];
}

// ---------------- t2 = h @ A2[id]^T (fp16 h). One block per row. ----------------
__global__ void __launch_bounds__(128)
tvec_h_kernel(const __half* __restrict__ H, const float* __restrict__ Afull,
              const int* __restrict__ idp, float* __restrict__ T) {
    const int m = blockIdx.x;
    const int tid = threadIdx.x;
    const float* Aa = Afull + (size_t)(*idp) * RANK * DFF;
    const __half* hr = H + (size_t)m * DFF;

    float s[4] = {0.f, 0.f, 0.f, 0.f};
#pragma unroll
    for (int i = 0; i < 4; ++i) {
        const int idx = i * 1024 + tid * 8;             // 8 contiguous halves/thread/iter
        uint4 pk = *reinterpret_cast<const uint4*>(hr + idx);
        const __half2* h2 = reinterpret_cast<const __half2*>(&pk);
        float vx[8];
#pragma unroll
        for (int p = 0; p < 4; ++p) {
            float2 f = __half22float2(h2[p]);
            vx[p * 2]     = f.x;
            vx[p * 2 + 1] = f.y;
        }
#pragma unroll
        for (int r = 0; r < RANK; ++r) {
            const float* ar = Aa + (size_t)r * DFF + idx;
            float4 a0 = *reinterpret_cast<const float4*>(ar);
            float4 a1 = *reinterpret_cast<const float4*>(ar + 4);
            s[r] += vx[0] * a0.x + vx[1] * a0.y + vx[2] * a0.z + vx[3] * a0.w
                  + vx[4] * a1.x + vx[5] * a1.y + vx[6] * a1.z + vx[7] * a1.w;
        }
    }
#pragma unroll
    for (int o = 16; o > 0; o >>= 1) {
#pragma unroll
        for (int r = 0; r < RANK; ++r) s[r] += __shfl_xor_sync(0xffffffffu, s[r], o);
    }
    __shared__ float red[4][4];
    const int wid = tid >> 5, lane = tid & 31;
    if (lane == 0) {
#pragma unroll
        for (int r = 0; r < RANK; ++r) red[wid][r] = s[r];
    }
    __syncthreads();
    if (tid < 4) T[(size_t)m * RANK + tid] = red[0][tid] + red[1][tid] + red[2][tid] + red[3][tid];
}

// ---------------- launch ----------------
extern "C" void kernel_launch(void* const* d_in, const int* in_sizes, int n_in,
                              void* d_out, int out_size) {
    (void)in_sizes; (void)n_in; (void)out_size;
    const float* x  = (const float*)d_in[0];
    const float* W1 = (const float*)d_in[1];
    const float* A1 = (const float*)d_in[2];
    const float* B1 = (const float*)d_in[3];
    const float* W2 = (const float*)d_in[4];
    const float* A2 = (const float*)d_in[5];
    const float* B2 = (const float*)d_in[6];
    const int*   id = (const int*)d_in[7];
    float* out = (float*)d_out;

    __half *xf, *w1f, *w2f, *hf;
    float *t1, *t2;
    cudaGetSymbolAddress((void**)&xf,  g_xf);
    cudaGetSymbolAddress((void**)&w1f, g_w1f);
    cudaGetSymbolAddress((void**)&w2f, g_w2f);
    cudaGetSymbolAddress((void**)&hf,  g_hf);
    cudaGetSymbolAddress((void**)&t1,  g_t1);
    cudaGetSymbolAddress((void**)&t2,  g_t2);

    cudaFuncSetAttribute((const void*)gemm_hmma_kernel<256, 4, true>,
                         cudaFuncAttributeMaxDynamicSharedMemorySize, SMEM_GEMM);
    cudaFuncSetAttribute((const void*)gemm_hmma_kernel<128, 6, false>,
                         cudaFuncAttributeMaxDynamicSharedMemorySize, SMEM_GEMM);

    // weight converts
    cvt_kernel<<<2048, 256>>>(W1, w1f, DFF * NE);
    cvt_kernel<<<2048, 256>>>(W2, w2f, NE * DFF);

    // t1 = x @ A1[id]^T fused with xf = fp16(x)
    tvec_x_kernel<<<M_TOK, 128>>>(x, A1, id, t1, xf);

    // h = relu(x W1^T + t1 B1^T * s), stored fp16   (BN=256, 4-stage)
    gemm_hmma_kernel<256, 4, true><<<dim3(DFF / 256, M_TOK / BM), 256, SMEM_GEMM>>>(
        xf, w1f, NE, DFF, t1, B1, id, hf, nullptr);

    // t2 = h @ A2[id]^T
    tvec_h_kernel<<<M_TOK, 128>>>(hf, A2, id, t2);

    // out = h W2^T + t2 B2^T * s  (fp32)           (BN=128, 6-stage: kills wave quant)
    gemm_hmma_kernel<128, 6, false><<<dim3(NE / 128, M_TOK / BM), 256, SMEM_GEMM>>>(
        hf, w2f, DFF, NE, t2, B2, id, nullptr, out);
}